// round 6
// baseline (speedup 1.0000x reference)
#include <cuda_runtime.h>
#include <stdint.h>

#define N_PTS   50000
#define B_ROWS  512
#define E_DIM   16
#define KSEL    20
#define KP1     21            // top-21; lane 0 is always "self", dropped at the end
#define TILE    128           // candidates per tile (1 per thread)
#define BTHR    128
#define G_ROWS  8
#define SPLITS  2
#define NGRP    (B_ROWS / G_ROWS)      // 64
#define NBLK    (NGRP * 2 * SPLITS)    // 256
#define HID     64
#define FULLM   0xffffffffu

typedef unsigned long long ull;

__device__ float g_feats[B_ROWS][8];
__device__ float g_pval[2][NGRP][SPLITS][G_ROWS][KP1];
__device__ int   g_pidx[2][NGRP][SPLITS][G_ROWS][KP1];
__device__ int   g_flag[2][NGRP];
__device__ int   g_done = 0;

static __device__ __forceinline__ float finf() { return __int_as_float(0x7f800000); }

static __device__ __forceinline__ ull pk2(float lo, float hi) {
    ull r; asm("mov.b64 %0,{%1,%2};" : "=l"(r) : "f"(lo), "f"(hi)); return r;
}
static __device__ __forceinline__ void upk2(ull v, float& lo, float& hi) {
    asm("mov.b64 {%0,%1},%2;" : "=f"(lo), "=f"(hi) : "l"(v));
}
static __device__ __forceinline__ ull fma2(ull a, ull b, ull c) {
    ull d; asm("fma.rn.f32x2 %0,%1,%2,%3;" : "=l"(d) : "l"(a), "l"(b), "l"(c)); return d;
}
static __device__ __forceinline__ ull add2(ull a, ull b) {
    ull d; asm("add.rn.f32x2 %0,%1,%2;" : "=l"(d) : "l"(a), "l"(b)); return d;
}

// ---------------------------------------------------------------------------
// grid = (64 groups, 2 sets, 2 splits) = 256 blocks of 128 threads.
// Every thread holds ALL 8 query rows in registers (255-reg budget, no smem
// q-broadcast, no duplicate candidate reads). 4 warps; warp w owns rows
// 2w, 2w+1 via two warp-distributed sorted top-21 lists.
// Pipeline per tile: prefetch(t+1) -> drain(t-1) -> compute+push(t) -> bar.
// ---------------------------------------------------------------------------
__global__ __launch_bounds__(BTHR)
void knn_kernel(const float* __restrict__ emb0, const float* __restrict__ emb1,
                const float* __restrict__ rctx0, const float* __restrict__ rctx1,
                const int* __restrict__ idx0, const int* __restrict__ idx1,
                const float* __restrict__ mean_in, const float* __restrict__ std_in,
                const float* __restrict__ W1, const float* __restrict__ b1,
                const float* __restrict__ Wm, const float* __restrict__ bm,
                const float* __restrict__ Ws, const float* __restrict__ bs,
                float* __restrict__ out, int n) {
    const int grp   = blockIdx.x;
    const int set   = blockIdx.y;
    const int split = blockIdx.z;
    const float* __restrict__ emb  = set ? emb1 : emb0;
    const float* __restrict__ rctx = set ? rctx1 : rctx0;
    const int*   __restrict__ idxp = set ? idx1 : idx0;

    const int rowbase = grp * G_ROWS;
    const int tid  = threadIdx.x;
    const int lane = tid & 31;
    const int w    = tid >> 5;          // warp 0..3: owns rows 2w, 2w+1

    __shared__ float qv_sm[2][G_ROWS][TILE];
    __shared__ int   qi_sm[2][G_ROWS][TILE];
    __shared__ int   qcnt[2][G_ROWS];
    __shared__ __align__(16) float thr_sm[G_ROWS];
    __shared__ int   smflag[2];

    // ---- all 8 query rows into registers (packed -2*q) ----
    ull q2[G_ROWS][8];
#pragma unroll
    for (int r = 0; r < G_ROWS; r++) {
        int si = idxp[rowbase + r];
        const float4* qp = reinterpret_cast<const float4*>(emb + (size_t)si * E_DIM);
#pragma unroll
        for (int c = 0; c < 4; c++) {
            float4 v = qp[c];
            q2[r][2 * c + 0] = pk2(-2.f * v.x, -2.f * v.y);
            q2[r][2 * c + 1] = pk2(-2.f * v.z, -2.f * v.w);
        }
    }

    if (tid < 16) qcnt[tid >> 3][tid & 7] = 0;
    if (tid < 8)  thr_sm[tid] = finf();
    __syncthreads();

    // ---- two top-21 lists per warp (rows 2w, 2w+1) ----
    float kv0 = finf(), kv1 = finf();
    int   ki0 = -1,     ki1 = -1;
    float th0 = finf(), th1 = finf();

    auto insert = [&](float& kv, int& ki, float& th, float bv, int bj) {
        float pv = __shfl_up_sync(FULLM, kv, 1);
        int   pj = __shfl_up_sync(FULLM, ki, 1);
        if (lane < KP1 && bv < kv) {
            if (lane == 0 || bv >= pv) { kv = bv; ki = bj; }
            else                        { kv = pv; ki = pj; }
        }
        th = __shfl_sync(FULLM, kv, KP1 - 1);
    };
    auto scatter = [&](float& kv, int& ki, float& th, float bvl, int bjl, bool act) {
        unsigned msk = __ballot_sync(FULLM, act && bvl < th);
        while (msk) {
            int src = __ffs(msk) - 1; msk &= msk - 1;
            float bv = __shfl_sync(FULLM, bvl, src);
            int   bj = __shfl_sync(FULLM, bjl, src);
            if (bv < th) insert(kv, ki, th, bv, bj);
        }
    };

    const int halfn  = (n + SPLITS - 1) / SPLITS;
    const int jbeg   = split * halfn;
    const int jend   = min(n, jbeg + halfn);
    const int ntiles = (jend - jbeg + TILE - 1) / TILE;

    // ================= warm-up: tile 0, direct per-warp =================
    for (int c = 0; c < 4; c++) {
        int j = jbeg + 32 * c + lane;
        bool act = (j < jend);
        float s0 = finf(), s1 = finf();
        if (act) {
            const ulonglong2* p = reinterpret_cast<const ulonglong2*>(emb + (size_t)j * E_DIM);
            ulonglong2 a = p[0], b = p[1], cc = p[2], d = p[3];
            ull e[8] = {a.x, a.y, b.x, b.y, cc.x, cc.y, d.x, d.y};
            ull nA = 0, nB = 0;
#pragma unroll
            for (int k = 0; k < 8; k += 2) {
                nA = fma2(e[k], e[k], nA);
                nB = fma2(e[k + 1], e[k + 1], nB);
            }
            ull nrm = add2(nA, nB);
            ull a0 = nrm, a1 = nrm;
#pragma unroll
            for (int k = 0; k < 8; k++) {
                a0 = fma2(q2[2 * w][k],     e[k], a0);
                a1 = fma2(q2[2 * w + 1][k], e[k], a1);
            }
            float lo, hi;
            upk2(a0, lo, hi); s0 = lo + hi;
            upk2(a1, lo, hi); s1 = lo + hi;
        }
        scatter(kv0, ki0, th0, s0, j, act);
        scatter(kv1, ki1, th1, s1, j, act);
    }
    if (lane == 0) { thr_sm[2 * w] = th0; thr_sm[2 * w + 1] = th1; }
    __syncthreads();

    // ================= pipelined main loop =================
    auto drain = [&](int buf, int r, float& kv, int& ki, float& th) {
        int m = qcnt[buf][r];
        for (int b0 = 0; b0 < m; b0 += 32) {
            bool  act = (b0 + lane < m);
            float bvl = act ? qv_sm[buf][r][b0 + lane] : finf();
            int   bjl = act ? qi_sm[buf][r][b0 + lane] : 0;
            scatter(kv, ki, th, bvl, bjl, act);
        }
        if (lane == 0) qcnt[buf][r] = 0;
    };

    auto body = [&](int t, ull (&eU)[8], bool vU, ull (&eP)[8], bool& vP) {
        // prefetch tile t+1
        {
            int jn = jbeg + (t + 1) * TILE + tid;
            vP = (jn < jend);
            if (vP) {
                const ulonglong2* p = reinterpret_cast<const ulonglong2*>(emb + (size_t)jn * E_DIM);
                ulonglong2 a = p[0], b = p[1], c = p[2], d = p[3];
                eP[0]=a.x; eP[1]=a.y; eP[2]=b.x; eP[3]=b.y;
                eP[4]=c.x; eP[5]=c.y; eP[6]=d.x; eP[7]=d.y;
            }
        }
        // threshold cache (state as of last barrier)
        float4 tA = *reinterpret_cast<const float4*>(&thr_sm[0]);
        float4 tB = *reinterpret_cast<const float4*>(&thr_sm[4]);
        float thr_c[8] = {tA.x, tA.y, tA.z, tA.w, tB.x, tB.y, tB.z, tB.w};
        // drain previous tile
        int bufp = (t - 1) & 1;
        drain(bufp, 2 * w,     kv0, ki0, th0);
        drain(bufp, 2 * w + 1, kv1, ki1, th1);
        if (lane == 0) { thr_sm[2 * w] = th0; thr_sm[2 * w + 1] = th1; }
        // compute + push tile t
        if (vU) {
            ull nA = 0, nB = 0;
#pragma unroll
            for (int k = 0; k < 8; k += 2) {
                nA = fma2(eU[k], eU[k], nA);
                nB = fma2(eU[k + 1], eU[k + 1], nB);
            }
            ull nrm = add2(nA, nB);
            ull acc[G_ROWS];
#pragma unroll
            for (int r = 0; r < G_ROWS; r++) acc[r] = nrm;
#pragma unroll
            for (int k = 0; k < 8; k++) {
                ull ek = eU[k];
#pragma unroll
                for (int r = 0; r < G_ROWS; r++)
                    acc[r] = fma2(q2[r][k], ek, acc[r]);
            }
            const int j   = jbeg + t * TILE + tid;
            const int buf = t & 1;
#pragma unroll
            for (int r = 0; r < G_ROWS; r++) {
                float lo, hi; upk2(acc[r], lo, hi);
                float s = lo + hi;
                if (s < thr_c[r]) {
                    int p = atomicAdd(&qcnt[buf][r], 1);
                    qv_sm[buf][r][p] = s;
                    qi_sm[buf][r][p] = j;
                }
            }
        }
        __syncthreads();
    };

    ull eC[8], eN[8];
    bool vC = false, vN = false;
    {   // preload tile 1
        int j = jbeg + TILE + tid;
        vC = (j < jend);
        if (vC) {
            const ulonglong2* p = reinterpret_cast<const ulonglong2*>(emb + (size_t)j * E_DIM);
            ulonglong2 a = p[0], b = p[1], c = p[2], d = p[3];
            eC[0]=a.x; eC[1]=a.y; eC[2]=b.x; eC[3]=b.y;
            eC[4]=c.x; eC[5]=c.y; eC[6]=d.x; eC[7]=d.y;
        }
    }
    for (int t = 1; t < ntiles; t += 2) {
        body(t, eC, vC, eN, vN);
        if (t + 1 < ntiles) body(t + 1, eN, vN, eC, vC);
    }
    // final drain
    {
        int bufl = (ntiles - 1) & 1;
        drain(bufl, 2 * w,     kv0, ki0, th0);
        drain(bufl, 2 * w + 1, kv1, ki1, th1);
    }

    // ================= split rendezvous =================
    if (lane < KP1) {
        g_pval[set][grp][split][2 * w][lane]     = kv0;
        g_pidx[set][grp][split][2 * w][lane]     = ki0;
        g_pval[set][grp][split][2 * w + 1][lane] = kv1;
        g_pidx[set][grp][split][2 * w + 1][lane] = ki1;
    }
    __threadfence();
    __syncthreads();
    if (tid == 0) smflag[0] = atomicAdd(&g_flag[set][grp], 1);
    __syncthreads();

    if (smflag[0] == 1) {                 // second arrival merges + features
        __threadfence();
        const int po = 1 - split;
#pragma unroll
        for (int rr = 0; rr < 2; rr++) {
            const int r = 2 * w + rr;
            float& kv = rr ? kv1 : kv0;
            int&   ki = rr ? ki1 : ki0;
            float& th = rr ? th1 : th0;
            for (int i = 0; i < KP1; i++) {
                float bv = g_pval[set][grp][po][r][i];
                int   bj = g_pidx[set][grp][po][r][i];
                if (bv < th) insert(kv, ki, th, bv, bj);
            }
            // |a|^2 from q2[r] (components are -2*a -> sum/4)
            ull t0 = 0;
#pragma unroll
            for (int k = 0; k < 8; k++) t0 = fma2(q2[r][k], q2[r][k], t0);
            float lo, hi; upk2(t0, lo, hi);
            float na = 0.25f * (lo + hi);
            // lane 0 holds "self" (s = -|a|^2, global min): drop it
            const int row = rowbase + r;
            float wgt = 0.f, sel = 0.f;
            if (lane >= 1 && lane < KP1) {
                float d2  = fmaxf(kv + na, 0.f);
                float sim = sqrtf(d2) + 0.001f;
                wgt = __expf(-sim);
                sel = rctx[(size_t)row * n + ki];
            }
            float sw = wgt, ssw = sel * wgt, ss = sel, ss2 = sel * sel;
#pragma unroll
            for (int off = 16; off; off >>= 1) {
                sw  += __shfl_xor_sync(FULLM, sw,  off);
                ssw += __shfl_xor_sync(FULLM, ssw, off);
                ss  += __shfl_xor_sync(FULLM, ss,  off);
                ss2 += __shfl_xor_sync(FULLM, ss2, off);
            }
            if (lane == 0) {
                g_feats[row][0 + set] = sw;
                g_feats[row][2 + set] = ssw / sw;
                float var = (ss2 - ss * ss / (float)KSEL) / (float)(KSEL - 1);
                g_feats[row][4 + set] = sqrtf(fmaxf(var, 0.f));
            }
        }
        if (tid == 0) g_flag[set][grp] = 0;
    }

    // ================= global tail: MLP =================
    __threadfence();
    __syncthreads();
    if (tid == 0) smflag[1] = atomicAdd(&g_done, 1);
    __syncthreads();
    if (smflag[1] != NBLK - 1) return;
    __threadfence();

#pragma unroll
    for (int rr = 0; rr < 4; rr++) {
        int r = tid + BTHR * rr;
        float f[8];
#pragma unroll
        for (int i = 0; i < 6; i++) f[i] = g_feats[r][i];
        f[6] = mean_in[r];
        f[7] = std_in[r];
        float m = bm[0], sd = bs[0];
#pragma unroll 4
        for (int jj = 0; jj < HID; jj++) {
            float h = b1[jj];
#pragma unroll
            for (int i = 0; i < 8; i++) h = fmaf(f[i], W1[i * HID + jj], h);
            h = fmaxf(h, 0.f);
            m  = fmaf(h, Wm[jj], m);
            sd = fmaf(h, Ws[jj], sd);
        }
        out[r]          = m;
        out[B_ROWS + r] = sd;
    }
    if (tid == 0) g_done = 0;
}

// ---------------------------------------------------------------------------
extern "C" void kernel_launch(void* const* d_in, const int* in_sizes, int n_in,
                              void* d_out, int out_size) {
    const float* emb0    = (const float*)d_in[0];
    const float* emb1    = (const float*)d_in[1];
    const float* rctx0   = (const float*)d_in[2];
    const float* rctx1   = (const float*)d_in[3];
    const int*   idx0    = (const int*)  d_in[4];
    const int*   idx1    = (const int*)  d_in[5];
    const float* mean_in = (const float*)d_in[6];
    const float* std_in  = (const float*)d_in[7];
    const float* W1      = (const float*)d_in[8];
    const float* b1      = (const float*)d_in[9];
    const float* Wm      = (const float*)d_in[10];
    const float* bm      = (const float*)d_in[11];
    const float* Ws      = (const float*)d_in[12];
    const float* bs      = (const float*)d_in[13];

    int n = in_sizes[0] / E_DIM;    // 50000

    dim3 grid(NGRP, 2, SPLITS);
    knn_kernel<<<grid, BTHR>>>(emb0, emb1, rctx0, rctx1, idx0, idx1,
                               mean_in, std_in, W1, b1, Wm, bm, Ws, bs,
                               (float*)d_out, n);
}

// round 7
// speedup vs baseline: 1.3720x; 1.3720x over previous
#include <cuda_runtime.h>
#include <stdint.h>

#define N_PTS   50000
#define B_ROWS  512
#define E_DIM   16
#define KSEL    20
#define TILE    512          // candidates per tile (2 per thread)
#define BTHR    256
#define G_ROWS  8
#define SPLITS  2
#define NGRP    (B_ROWS / G_ROWS)      // 64
#define NBLK    (NGRP * 2 * SPLITS)    // 256
#define HID     64
#define FULLM   0xffffffffu

typedef unsigned long long ull;

__device__ float g_feats[B_ROWS][8];
__device__ float g_pval[2][NGRP][SPLITS][G_ROWS][KSEL];
__device__ int   g_pidx[2][NGRP][SPLITS][G_ROWS][KSEL];
__device__ int   g_flag[2][NGRP];
__device__ int   g_done = 0;

static __device__ __forceinline__ float finf() { return __int_as_float(0x7f800000); }

static __device__ __forceinline__ ull pk2(float lo, float hi) {
    ull r; asm("mov.b64 %0,{%1,%2};" : "=l"(r) : "f"(lo), "f"(hi)); return r;
}
static __device__ __forceinline__ void upk2(ull v, float& lo, float& hi) {
    asm("mov.b64 {%0,%1},%2;" : "=f"(lo), "=f"(hi) : "l"(v));
}
static __device__ __forceinline__ ull fma2(ull a, ull b, ull c) {
    ull d; asm("fma.rn.f32x2 %0,%1,%2,%3;" : "=l"(d) : "l"(a), "l"(b), "l"(c)); return d;
}
static __device__ __forceinline__ ull add2(ull a, ull b) {
    ull d; asm("add.rn.f32x2 %0,%1,%2;" : "=l"(d) : "l"(a), "l"(b)); return d;
}

// ---------------------------------------------------------------------------
// grid = (64 groups, 2 sets, 2 splits) = 256 blocks x 256 threads (occ 2/SM).
// Phase A: thread computes s = |e|^2 - 2 a_r.e for 2 candidates x 8 rows
//          (q broadcast from smem) and stores to sbuf[row][cand] (coalesced).
// Phase B: warp w scans row w of the tile: 4 LDS.128 + hitmask + redux;
//          warp-distributed sorted top-20 insert on hits only.
// ---------------------------------------------------------------------------
__global__ __launch_bounds__(BTHR, 2)
void knn_kernel(const float* __restrict__ emb0, const float* __restrict__ emb1,
                const float* __restrict__ rctx0, const float* __restrict__ rctx1,
                const int* __restrict__ idx0, const int* __restrict__ idx1,
                const float* __restrict__ mean_in, const float* __restrict__ std_in,
                const float* __restrict__ W1, const float* __restrict__ b1,
                const float* __restrict__ Wm, const float* __restrict__ bm,
                const float* __restrict__ Ws, const float* __restrict__ bs,
                float* __restrict__ out, int n) {
    const int grp   = blockIdx.x;
    const int set   = blockIdx.y;
    const int split = blockIdx.z;
    const float* __restrict__ emb  = set ? emb1 : emb0;
    const float* __restrict__ rctx = set ? rctx1 : rctx0;
    const int*   __restrict__ idxp = set ? idx1 : idx0;

    const int rowbase = grp * G_ROWS;
    const int tid  = threadIdx.x;
    const int lane = tid & 31;
    const int w    = tid >> 5;              // warp id == local row id

    __shared__ __align__(16) ull q_sm[8][8];   // [c][r]: pack(-2q[r][2c],-2q[r][2c+1])
    __shared__ float na_sm[8];
    __shared__ int   self_sm[8];
    __shared__ float sbuf[2][G_ROWS][TILE];    // [buf][row][cand] -> coalesced
    __shared__ int   smflag[2];

    // ---- stage queries: warp r handles row r ----
    if (w < G_ROWS) {
        int si = 0;
        if (lane == 0) si = idxp[rowbase + w];
        si = __shfl_sync(FULLM, si, 0);
        if (lane == 0) self_sm[w] = si;
        float nx = 0.f;
        if (lane < 8) {
            float2 v = reinterpret_cast<const float2*>(emb + (size_t)si * E_DIM)[lane];
            nx = v.x * v.x + v.y * v.y;
            q_sm[lane][w] = pk2(-2.f * v.x, -2.f * v.y);
        }
        nx += __shfl_xor_sync(FULLM, nx, 4);
        nx += __shfl_xor_sync(FULLM, nx, 2);
        nx += __shfl_xor_sync(FULLM, nx, 1);
        if (lane == 0) na_sm[w] = nx;
    }
    __syncthreads();
    const int   selfi = self_sm[w];
    const float na    = na_sm[w];

    const int halfn  = (n + SPLITS - 1) / SPLITS;
    const int jbeg   = split * halfn;
    const int jend   = min(n, jbeg + halfn);
    const int ntiles = (jend - jbeg + TILE - 1) / TILE;

    // ---- top-k state (lanes 0..19 ascending) ----
    float kval   = finf();
    int   kidx   = -1;
    float thresh = finf();

    auto insert = [&](float bv, int bj) {
        float pv = __shfl_up_sync(FULLM, kval, 1);
        int   pj = __shfl_up_sync(FULLM, kidx, 1);
        if (lane < KSEL && bv < kval) {
            if (lane == 0 || bv >= pv) { kval = bv; kidx = bj; }
            else                        { kval = pv; kidx = pj; }
        }
        thresh = __shfl_sync(FULLM, kval, KSEL - 1);
    };

    // ---- Phase B: warp w scans row w of buffer buf (coalesced LDS.128) ----
    auto phaseB = [&](int t) {
        const int buf  = t & 1;
        const int base = jbeg + t * TILE;
        const float4* rp = reinterpret_cast<const float4*>(&sbuf[buf][w][0]);
        float v[16];
#pragma unroll
        for (int it = 0; it < 4; it++) {
            float4 f4 = rp[lane + 32 * it];
            v[4 * it + 0] = f4.x; v[4 * it + 1] = f4.y;
            v[4 * it + 2] = f4.z; v[4 * it + 3] = f4.w;
        }
        unsigned hm = 0;
#pragma unroll
        for (int i = 0; i < 16; i++) {
            int j = base + 128 * (i >> 2) + 4 * lane + (i & 3);
            if (v[i] < thresh && j != selfi) hm |= (1u << i);
        }
        unsigned red = __reduce_or_sync(FULLM, hm);
        while (red) {
            int i = __ffs(red) - 1; red &= red - 1;
            unsigned m = __ballot_sync(FULLM, (hm >> i) & 1u);
            float vi = v[i];
            int   ji = base + 128 * (i >> 2) + 4 * lane + (i & 3);
            while (m) {
                int src = __ffs(m) - 1; m &= m - 1;
                float bv = __shfl_sync(FULLM, vi, src);
                int   bj = __shfl_sync(FULLM, ji, src);
                if (bv < thresh) insert(bv, bj);
            }
        }
    };

    // ---- main loop: load -> phaseA -> bar -> phaseB (double-buffered) ----
    for (int t = 0; t < ntiles; t++) {
        const int j0 = jbeg + t * TILE + tid;
        const int j1 = j0 + BTHR;
        const bool v0 = (j0 < jend), v1 = (j1 < jend);
        ull e0[8], e1[8];
        if (v0) {
            const ulonglong2* p = reinterpret_cast<const ulonglong2*>(emb + (size_t)j0 * E_DIM);
            ulonglong2 a = p[0], b = p[1], c = p[2], d = p[3];
            e0[0]=a.x; e0[1]=a.y; e0[2]=b.x; e0[3]=b.y; e0[4]=c.x; e0[5]=c.y; e0[6]=d.x; e0[7]=d.y;
        }
        if (v1) {
            const ulonglong2* p = reinterpret_cast<const ulonglong2*>(emb + (size_t)j1 * E_DIM);
            ulonglong2 a = p[0], b = p[1], c = p[2], d = p[3];
            e1[0]=a.x; e1[1]=a.y; e1[2]=b.x; e1[3]=b.y; e1[4]=c.x; e1[5]=c.y; e1[6]=d.x; e1[7]=d.y;
        }

        if (t > 0) phaseB(t - 1);        // overlap with in-flight LDGs

        const int buf = t & 1;
        ull n0A = 0, n0B = 0, n1A = 0, n1B = 0;
#pragma unroll
        for (int c = 0; c < 8; c += 2) {
            n0A = fma2(e0[c], e0[c], n0A);   n0B = fma2(e0[c+1], e0[c+1], n0B);
            n1A = fma2(e1[c], e1[c], n1A);   n1B = fma2(e1[c+1], e1[c+1], n1B);
        }
        ull nrm0 = add2(n0A, n0B), nrm1 = add2(n1A, n1B);
        ull acc0[8], acc1[8];
#pragma unroll
        for (int r = 0; r < 8; r++) { acc0[r] = nrm0; acc1[r] = nrm1; }
#pragma unroll
        for (int c = 0; c < 8; c++) {
            const ulonglong2* qp = reinterpret_cast<const ulonglong2*>(&q_sm[c][0]);
#pragma unroll
            for (int p = 0; p < 4; p++) {
                ulonglong2 qv = qp[p];      // broadcast LDS.128
                acc0[2*p]   = fma2(qv.x, e0[c], acc0[2*p]);
                acc0[2*p+1] = fma2(qv.y, e0[c], acc0[2*p+1]);
                acc1[2*p]   = fma2(qv.x, e1[c], acc1[2*p]);
                acc1[2*p+1] = fma2(qv.y, e1[c], acc1[2*p+1]);
            }
        }
#pragma unroll
        for (int r = 0; r < 8; r++) {       // coalesced row-major stores
            float lo, hi;
            upk2(acc0[r], lo, hi);
            sbuf[buf][r][tid]        = v0 ? (lo + hi) : finf();
            upk2(acc1[r], lo, hi);
            sbuf[buf][r][tid + BTHR] = v1 ? (lo + hi) : finf();
        }
        __syncthreads();
    }
    phaseB(ntiles - 1);

    // ---- split rendezvous: per-split partial slots ----
    if (lane < KSEL) {
        g_pval[set][grp][split][w][lane] = kval;
        g_pidx[set][grp][split][w][lane] = kidx;
    }
    __threadfence();
    __syncthreads();
    if (tid == 0) smflag[0] = atomicAdd(&g_flag[set][grp], 1);
    __syncthreads();

    if (smflag[0] == 1) {                 // second arrival merges + features
        __threadfence();
        const int po = 1 - split;
        for (int i = 0; i < KSEL; i++) {
            float bv = g_pval[set][grp][po][w][i];
            int   bj = g_pidx[set][grp][po][w][i];
            if (bv < thresh) insert(bv, bj);
        }
        const int row = rowbase + w;
        float wgt = 0.f, sel = 0.f;
        if (lane < KSEL) {
            float d2  = fmaxf(kval + na, 0.f);
            float sim = sqrtf(d2) + 0.001f;
            wgt = __expf(-sim);
            sel = rctx[(size_t)row * n + kidx];
        }
        float sw = wgt, ssw = sel * wgt, ss = sel, ss2 = sel * sel;
#pragma unroll
        for (int off = 16; off; off >>= 1) {
            sw  += __shfl_xor_sync(FULLM, sw,  off);
            ssw += __shfl_xor_sync(FULLM, ssw, off);
            ss  += __shfl_xor_sync(FULLM, ss,  off);
            ss2 += __shfl_xor_sync(FULLM, ss2, off);
        }
        if (lane == 0) {
            g_feats[row][0 + set] = sw;
            g_feats[row][2 + set] = ssw / sw;
            float var = (ss2 - ss * ss / (float)KSEL) / (float)(KSEL - 1);
            g_feats[row][4 + set] = sqrtf(fmaxf(var, 0.f));
        }
        if (tid == 0) g_flag[set][grp] = 0;
    }

    // ---- global tail: MLP ----
    __threadfence();
    __syncthreads();
    if (tid == 0) smflag[1] = atomicAdd(&g_done, 1);
    __syncthreads();
    if (smflag[1] != NBLK - 1) return;
    __threadfence();

#pragma unroll
    for (int rr = 0; rr < 2; rr++) {
        int r = tid + BTHR * rr;
        float f[8];
#pragma unroll
        for (int i = 0; i < 6; i++) f[i] = g_feats[r][i];
        f[6] = mean_in[r];
        f[7] = std_in[r];
        float m = bm[0], sd = bs[0];
#pragma unroll 4
        for (int jj = 0; jj < HID; jj++) {
            float h = b1[jj];
#pragma unroll
            for (int i = 0; i < 8; i++) h = fmaf(f[i], W1[i * HID + jj], h);
            h = fmaxf(h, 0.f);
            m  = fmaf(h, Wm[jj], m);
            sd = fmaf(h, Ws[jj], sd);
        }
        out[r]          = m;
        out[B_ROWS + r] = sd;
    }
    if (tid == 0) g_done = 0;
}

// ---------------------------------------------------------------------------
extern "C" void kernel_launch(void* const* d_in, const int* in_sizes, int n_in,
                              void* d_out, int out_size) {
    const float* emb0    = (const float*)d_in[0];
    const float* emb1    = (const float*)d_in[1];
    const float* rctx0   = (const float*)d_in[2];
    const float* rctx1   = (const float*)d_in[3];
    const int*   idx0    = (const int*)  d_in[4];
    const int*   idx1    = (const int*)  d_in[5];
    const float* mean_in = (const float*)d_in[6];
    const float* std_in  = (const float*)d_in[7];
    const float* W1      = (const float*)d_in[8];
    const float* b1      = (const float*)d_in[9];
    const float* Wm      = (const float*)d_in[10];
    const float* bm      = (const float*)d_in[11];
    const float* Ws      = (const float*)d_in[12];
    const float* bs      = (const float*)d_in[13];

    int n = in_sizes[0] / E_DIM;    // 50000

    dim3 grid(NGRP, 2, SPLITS);
    knn_kernel<<<grid, BTHR>>>(emb0, emb1, rctx0, rctx1, idx0, idx1,
                               mean_in, std_in, W1, b1, Wm, bm, Ws, bs,
                               (float*)d_out, n);
}